// round 1
// baseline (speedup 1.0000x reference)
#include <cuda_runtime.h>
#include <math.h>

#define BB 2
#define SS 2048
#define DD 1024
#define HH 16
#define DHH 64
#define PSTR 65

// Scratch (allocation-free): head-major q/k/v and attention output
__device__ float g_qh[BB * SS * DD];
__device__ float g_kh[BB * SS * DD];
__device__ float g_vh[BB * SS * DD];
__device__ float g_att[BB * SS * DD];

// ---------------------------------------------------------------------------
// GEMM: C[m][n] = sum_k A[m][k] * W[n][k] + bias[n]
// A: [M=4096, 1024] row-major, W: [1024, 1024] row-major (nn.Linear weight)
// Tile: BM=128, BN=64, BK=16, 256 threads, 8x4 per-thread register tile.
// HEAD_OUT: write output in [B,H,S,DH] head-major layout (for q/k/v).
// ---------------------------------------------------------------------------
template <bool HEAD_OUT>
__device__ __forceinline__ void gemm_body(const float* __restrict__ A,
                                          const float* __restrict__ W,
                                          const float* __restrict__ bias,
                                          float* __restrict__ out) {
    __shared__ float As[16][128];
    __shared__ float Ws[16][64];
    const int t = threadIdx.x;
    const int tx = t & 15, ty = t >> 4;
    const int m0 = blockIdx.y * 128, n0 = blockIdx.x * 64;

    float acc[8][4];
#pragma unroll
    for (int i = 0; i < 8; i++)
#pragma unroll
        for (int j = 0; j < 4; j++) acc[i][j] = 0.f;

    for (int k0 = 0; k0 < DD; k0 += 16) {
        // Load A tile (128x16) transposed into smem: 2 float4 per thread
#pragma unroll
        for (int li = 0; li < 2; li++) {
            int f = t + li * 256;
            int row = f >> 2, kc = (f & 3) * 4;
            float4 v = *(const float4*)&A[(size_t)(m0 + row) * DD + k0 + kc];
            As[kc + 0][row] = v.x;
            As[kc + 1][row] = v.y;
            As[kc + 2][row] = v.z;
            As[kc + 3][row] = v.w;
        }
        // Load W tile (64x16) transposed: 1 float4 per thread
        {
            int row = t >> 2, kc = (t & 3) * 4;
            float4 v = *(const float4*)&W[(size_t)(n0 + row) * DD + k0 + kc];
            Ws[kc + 0][row] = v.x;
            Ws[kc + 1][row] = v.y;
            Ws[kc + 2][row] = v.z;
            Ws[kc + 3][row] = v.w;
        }
        __syncthreads();
#pragma unroll
        for (int k = 0; k < 16; k++) {
            float4 a0 = *(const float4*)&As[k][ty * 8];
            float4 a1 = *(const float4*)&As[k][ty * 8 + 4];
            float4 b0 = *(const float4*)&Ws[k][tx * 4];
            float ar[8] = {a0.x, a0.y, a0.z, a0.w, a1.x, a1.y, a1.z, a1.w};
            float br[4] = {b0.x, b0.y, b0.z, b0.w};
#pragma unroll
            for (int i = 0; i < 8; i++)
#pragma unroll
                for (int j = 0; j < 4; j++)
                    acc[i][j] = fmaf(ar[i], br[j], acc[i][j]);
        }
        __syncthreads();
    }

    float4 bb = *(const float4*)&bias[n0 + tx * 4];
    float br[4] = {bb.x, bb.y, bb.z, bb.w};
#pragma unroll
    for (int i = 0; i < 8; i++) {
        int m = m0 + ty * 8 + i;
#pragma unroll
        for (int j = 0; j < 4; j++) {
            int n = n0 + tx * 4 + j;
            float v = acc[i][j] + br[j];
            if (HEAD_OUT) {
                int b = m >> 11, s = m & (SS - 1);
                int h = n >> 6, dh = n & 63;
                out[(((size_t)(b * HH + h) * SS + s) << 6) + dh] = v;
            } else {
                out[(size_t)m * DD + n] = v;
            }
        }
    }
}

__global__ void __launch_bounds__(256) proj_kernel(
    const float* __restrict__ Q, const float* __restrict__ K,
    const float* __restrict__ V, const float* __restrict__ Wq,
    const float* __restrict__ bq, const float* __restrict__ Wk,
    const float* __restrict__ bk, const float* __restrict__ Wv,
    const float* __restrict__ bv) {
    int z = blockIdx.z;
    const float* A = (z == 0) ? Q : (z == 1) ? K : V;
    const float* W = (z == 0) ? Wq : (z == 1) ? Wk : Wv;
    const float* bias = (z == 0) ? bq : (z == 1) ? bk : bv;
    float* out = (z == 0) ? g_qh : (z == 1) ? g_kh : g_vh;
    gemm_body<true>(A, W, bias, out);
}

__global__ void __launch_bounds__(256) oproj_kernel(const float* __restrict__ Wo,
                                                    const float* __restrict__ bo,
                                                    float* __restrict__ out) {
    gemm_body<false>(g_att, Wo, bo, out);
}

// ---------------------------------------------------------------------------
// Flash-style causal attention. Grid: (S/64 query blocks, B*H).
// 256 threads; 64x64 score tile with 4x4 per-thread fragment; online softmax;
// P staged through padded smem for the PV GEMM. Causal: only kb <= qb blocks.
// ---------------------------------------------------------------------------
__global__ void __launch_bounds__(256) attn_kernel(const int* __restrict__ mask) {
    extern __shared__ float sm[];
    float* Qs = sm;           // [64][64] transposed: Qs[d][row]
    float* Ks = sm + 4096;    // [64][64] transposed: Ks[d][col]
    float* Vs = sm + 8192;    // [64][64] natural:    Vs[key][dh]
    float* Ps = sm + 12288;   // [64][PSTR]:          Ps[key][row]

    const int t = threadIdx.x;
    const int tx = t & 15, ty = t >> 4;
    const int qb = blockIdx.x;  // 0..31
    const int bh = blockIdx.y;  // 0..31
    const int b = bh >> 4;
    const int h = bh & 15;
    const size_t base = (size_t)bh * SS * DHH;
    const float* Qp = g_qh + base;
    const float* Kp = g_kh + base;
    const float* Vp = g_vh + base;

    // Load Q tile transposed (4 float4 per thread)
#pragma unroll
    for (int li = 0; li < 4; li++) {
        int f = t + li * 256;
        int row = f >> 4, c = (f & 15) * 4;
        float4 v = *(const float4*)&Qp[(size_t)(qb * 64 + row) * 64 + c];
        Qs[(c + 0) * 64 + row] = v.x;
        Qs[(c + 1) * 64 + row] = v.y;
        Qs[(c + 2) * 64 + row] = v.z;
        Qs[(c + 3) * 64 + row] = v.w;
    }

    float m_r[4], l_r[4], acc[4][4];
#pragma unroll
    for (int i = 0; i < 4; i++) {
        m_r[i] = -INFINITY;
        l_r[i] = 0.f;
#pragma unroll
        for (int j = 0; j < 4; j++) acc[i][j] = 0.f;
    }

    const float scale = 0.125f;  // 1/sqrt(64)

    for (int kb = 0; kb <= qb; kb++) {
        __syncthreads();  // prior PV done before overwriting K/V
        // Load K transposed + V natural
#pragma unroll
        for (int li = 0; li < 4; li++) {
            int f = t + li * 256;
            int row = f >> 4, c = (f & 15) * 4;
            float4 kv = *(const float4*)&Kp[(size_t)(kb * 64 + row) * 64 + c];
            Ks[(c + 0) * 64 + row] = kv.x;
            Ks[(c + 1) * 64 + row] = kv.y;
            Ks[(c + 2) * 64 + row] = kv.z;
            Ks[(c + 3) * 64 + row] = kv.w;
            float4 vv = *(const float4*)&Vp[(size_t)(kb * 64 + row) * 64 + c];
            *(float4*)&Vs[row * 64 + c] = vv;
        }
        __syncthreads();

        // Scores: s[i][j] = q_row . k_col
        float s[4][4];
#pragma unroll
        for (int i = 0; i < 4; i++)
#pragma unroll
            for (int j = 0; j < 4; j++) s[i][j] = 0.f;
#pragma unroll 16
        for (int d = 0; d < 64; d++) {
            float4 qv = *(const float4*)&Qs[d * 64 + ty * 4];
            float4 kv = *(const float4*)&Ks[d * 64 + tx * 4];
            float qr[4] = {qv.x, qv.y, qv.z, qv.w};
            float kr[4] = {kv.x, kv.y, kv.z, kv.w};
#pragma unroll
            for (int i = 0; i < 4; i++)
#pragma unroll
                for (int j = 0; j < 4; j++)
                    s[i][j] = fmaf(qr[i], kr[j], s[i][j]);
        }

        // Scale + padding/causal mask
        const int kg0 = kb * 64 + tx * 4;
        int mk[4];
#pragma unroll
        for (int j = 0; j < 4; j++) mk[j] = mask[b * SS + kg0 + j];
#pragma unroll
        for (int j = 0; j < 4; j++) {
#pragma unroll
            for (int i = 0; i < 4; i++) {
                int ig = qb * 64 + ty * 4 + i;
                float v = s[i][j] * scale;
                if (mk[j] == 0 || (kg0 + j) > ig) v = -INFINITY;
                s[i][j] = v;
            }
        }

        // Online softmax (row reduction over the 16-lane tx group)
#pragma unroll
        for (int i = 0; i < 4; i++) {
            float rm = fmaxf(fmaxf(s[i][0], s[i][1]), fmaxf(s[i][2], s[i][3]));
#pragma unroll
            for (int off = 8; off > 0; off >>= 1)
                rm = fmaxf(rm, __shfl_xor_sync(0xffffffffu, rm, off));
            float mnew = fmaxf(m_r[i], rm);
            float scl = __expf(m_r[i] - mnew);
            float ps = 0.f;
#pragma unroll
            for (int j = 0; j < 4; j++) {
                float p = __expf(s[i][j] - mnew);
                s[i][j] = p;
                ps += p;
            }
#pragma unroll
            for (int off = 8; off > 0; off >>= 1)
                ps += __shfl_xor_sync(0xffffffffu, ps, off);
            l_r[i] = l_r[i] * scl + ps;
            m_r[i] = mnew;
#pragma unroll
            for (int j = 0; j < 4; j++) acc[i][j] *= scl;
        }

        // Stage P transposed: Ps[key][row]
#pragma unroll
        for (int j = 0; j < 4; j++)
#pragma unroll
            for (int i = 0; i < 4; i++)
                Ps[(tx * 4 + j) * PSTR + ty * 4 + i] = s[i][j];
        __syncthreads();

        // PV: acc[i][j] += sum_kk P[row][kk] * V[kk][dh]
#pragma unroll 8
        for (int kk = 0; kk < 64; kk++) {
            float4 vv = *(const float4*)&Vs[kk * 64 + tx * 4];
            float vr[4] = {vv.x, vv.y, vv.z, vv.w};
            float pr[4];
#pragma unroll
            for (int i = 0; i < 4; i++) pr[i] = Ps[kk * PSTR + ty * 4 + i];
#pragma unroll
            for (int i = 0; i < 4; i++)
#pragma unroll
                for (int j = 0; j < 4; j++)
                    acc[i][j] = fmaf(pr[i], vr[j], acc[i][j]);
        }
    }

    // Normalize + write back to [B,S,D] scratch for output projection
#pragma unroll
    for (int i = 0; i < 4; i++) {
        float inv = 1.0f / l_r[i];
        int row = qb * 64 + ty * 4 + i;
        size_t o = ((size_t)(b * SS + row)) * DD + h * 64 + tx * 4;
        float4 w;
        w.x = acc[i][0] * inv;
        w.y = acc[i][1] * inv;
        w.z = acc[i][2] * inv;
        w.w = acc[i][3] * inv;
        *(float4*)&g_att[o] = w;
    }
}

// ---------------------------------------------------------------------------
extern "C" void kernel_launch(void* const* d_in, const int* in_sizes, int n_in,
                              void* d_out, int out_size) {
    const float* Q = (const float*)d_in[0];
    const float* K = (const float*)d_in[1];
    const float* V = (const float*)d_in[2];
    const int* mask = (const int*)d_in[3];
    const float* Wq = (const float*)d_in[4];
    const float* bq = (const float*)d_in[5];
    const float* Wk = (const float*)d_in[6];
    const float* bk = (const float*)d_in[7];
    const float* Wv = (const float*)d_in[8];
    const float* bv = (const float*)d_in[9];
    const float* Wo = (const float*)d_in[10];
    const float* bo = (const float*)d_in[11];
    float* out = (float*)d_out;

    // QKV projections into head-major scratch
    dim3 gproj(DD / 64, (BB * SS) / 128, 3);
    proj_kernel<<<gproj, 256>>>(Q, K, V, Wq, bq, Wk, bk, Wv, bv);

    // Attention (dynamic smem: 3*64*64 + 64*PSTR floats = 65792 B)
    const int smem_attn = (3 * 4096 + 64 * PSTR) * (int)sizeof(float);
    cudaFuncSetAttribute(attn_kernel, cudaFuncAttributeMaxDynamicSharedMemorySize,
                         smem_attn);
    dim3 gattn(SS / 64, BB * HH);
    attn_kernel<<<gattn, 256, smem_attn>>>(mask);

    // Output projection straight into d_out
    dim3 gout(DD / 64, (BB * SS) / 128);
    oproj_kernel<<<gout, 256>>>(Wo, bo, out);
}

// round 2
// speedup vs baseline: 1.6190x; 1.6190x over previous
#include <cuda_runtime.h>
#include <math.h>
#include <stdint.h>

#define BB 2
#define SS 2048
#define DD 1024
#define HH 16
#define DHH 64
#define PSTR 65

// Scratch (allocation-free): head-major q/k/v and attention output
__device__ float g_qh[BB * SS * DD];
__device__ float g_kh[BB * SS * DD];
__device__ float g_vh[BB * SS * DD];
__device__ float g_att[BB * SS * DD];

// ---------------------------------------------------------------------------
// TF32 helpers
// ---------------------------------------------------------------------------
__device__ __forceinline__ uint32_t f2tf(float f) {
    uint32_t u;
    asm("cvt.rna.tf32.f32 %0, %1;" : "=r"(u) : "f"(f));
    return u;
}

__device__ __forceinline__ void mma_tf32(float* c, const uint32_t* a,
                                         const uint32_t* b) {
    asm volatile(
        "mma.sync.aligned.m16n8k8.row.col.f32.tf32.tf32.f32 "
        "{%0,%1,%2,%3}, {%4,%5,%6,%7}, {%8,%9}, {%0,%1,%2,%3};\n"
        : "+f"(c[0]), "+f"(c[1]), "+f"(c[2]), "+f"(c[3])
        : "r"(a[0]), "r"(a[1]), "r"(a[2]), "r"(a[3]), "r"(b[0]), "r"(b[1]));
}

// ---------------------------------------------------------------------------
// TF32 tensor-core GEMM: C[m][n] = sum_k A[m][k] * W[n][k] + bias[n]
// A: [4096,1024] row-major, W: [1024,1024] row-major (nn.Linear weight ==
// col-major B operand for mma row.col). Block tile 128x128x32, 8 warps (4x2),
// warp tile 32x64 built from m16n8k8 fragments.
// Smem stride 36 words -> fragment LDS bank == lane (conflict-free).
// ---------------------------------------------------------------------------
template <bool HEAD_OUT>
__device__ __forceinline__ void gemm_tc(const float* __restrict__ A,
                                        const float* __restrict__ W,
                                        const float* __restrict__ bias,
                                        float* __restrict__ out) {
    __shared__ uint32_t As[128 * 36];
    __shared__ uint32_t Ws[128 * 36];
    const int t = threadIdx.x;
    const int lane = t & 31, warp = t >> 5;
    const int wm = (warp >> 1) * 32;  // warp row offset in block tile
    const int wn = (warp & 1) * 64;   // warp col offset
    const int g = lane >> 2, tg = lane & 3;
    const int m0 = blockIdx.y * 128, n0 = blockIdx.x * 128;

    float acc[2][8][4];
#pragma unroll
    for (int mt = 0; mt < 2; mt++)
#pragma unroll
        for (int nt = 0; nt < 8; nt++)
#pragma unroll
            for (int i = 0; i < 4; i++) acc[mt][nt][i] = 0.f;

    const int lrow = t >> 3, lcol = (t & 7) * 4;

    for (int k0 = 0; k0 < DD; k0 += 32) {
        // Stage A and W tiles (128x32 each), converting to tf32 once here.
#pragma unroll
        for (int it = 0; it < 4; it++) {
            int r = lrow + it * 32;
            float4 av = *(const float4*)&A[(size_t)(m0 + r) * DD + k0 + lcol];
            uint4 au = {f2tf(av.x), f2tf(av.y), f2tf(av.z), f2tf(av.w)};
            *(uint4*)&As[r * 36 + lcol] = au;
            float4 wv = *(const float4*)&W[(size_t)(n0 + r) * DD + k0 + lcol];
            uint4 wu = {f2tf(wv.x), f2tf(wv.y), f2tf(wv.z), f2tf(wv.w)};
            *(uint4*)&Ws[r * 36 + lcol] = wu;
        }
        __syncthreads();

#pragma unroll
        for (int ks = 0; ks < 4; ks++) {
            const int kk = ks * 8;
            uint32_t a[2][4], b[8][2];
#pragma unroll
            for (int mt = 0; mt < 2; mt++) {
                int rb = wm + mt * 16 + g;
                a[mt][0] = As[rb * 36 + kk + tg];
                a[mt][1] = As[(rb + 8) * 36 + kk + tg];
                a[mt][2] = As[rb * 36 + kk + 4 + tg];
                a[mt][3] = As[(rb + 8) * 36 + kk + 4 + tg];
            }
#pragma unroll
            for (int nt = 0; nt < 8; nt++) {
                int cb = wn + nt * 8 + g;
                b[nt][0] = Ws[cb * 36 + kk + tg];
                b[nt][1] = Ws[cb * 36 + kk + 4 + tg];
            }
#pragma unroll
            for (int mt = 0; mt < 2; mt++)
#pragma unroll
                for (int nt = 0; nt < 8; nt++)
                    mma_tf32(acc[mt][nt], a[mt], b[nt]);
        }
        __syncthreads();
    }

    // Epilogue: c0,c1 -> row g; c2,c3 -> row g+8; cols 2*tg, 2*tg+1.
#pragma unroll
    for (int mt = 0; mt < 2; mt++) {
#pragma unroll
        for (int i = 0; i < 2; i++) {
            int m = m0 + wm + mt * 16 + g + i * 8;
#pragma unroll
            for (int nt = 0; nt < 8; nt++) {
                int n = n0 + wn + nt * 8 + tg * 2;
                float2 v;
                v.x = acc[mt][nt][i * 2 + 0] + bias[n];
                v.y = acc[mt][nt][i * 2 + 1] + bias[n + 1];
                if (HEAD_OUT) {
                    int bI = m >> 11, s = m & (SS - 1);
                    int h = n >> 6, dh = n & 63;
                    *(float2*)&out[(((size_t)(bI * HH + h) * SS + s) << 6) + dh] = v;
                } else {
                    *(float2*)&out[(size_t)m * DD + n] = v;
                }
            }
        }
    }
}

__global__ void __launch_bounds__(256) proj_kernel(
    const float* __restrict__ Q, const float* __restrict__ K,
    const float* __restrict__ V, const float* __restrict__ Wq,
    const float* __restrict__ bq, const float* __restrict__ Wk,
    const float* __restrict__ bk, const float* __restrict__ Wv,
    const float* __restrict__ bv) {
    int z = blockIdx.z;
    const float* A = (z == 0) ? Q : (z == 1) ? K : V;
    const float* W = (z == 0) ? Wq : (z == 1) ? Wk : Wv;
    const float* bias = (z == 0) ? bq : (z == 1) ? bk : bv;
    float* out = (z == 0) ? g_qh : (z == 1) ? g_kh : g_vh;
    gemm_tc<true>(A, W, bias, out);
}

__global__ void __launch_bounds__(256) oproj_kernel(const float* __restrict__ Wo,
                                                    const float* __restrict__ bo,
                                                    float* __restrict__ out) {
    gemm_tc<false>(g_att, Wo, bo, out);
}

// ---------------------------------------------------------------------------
// Flash-style causal attention (unchanged from R1). Grid: (S/64, B*H).
// ---------------------------------------------------------------------------
__global__ void __launch_bounds__(256) attn_kernel(const int* __restrict__ mask) {
    extern __shared__ float sm[];
    float* Qs = sm;           // [64][64] transposed: Qs[d][row]
    float* Ks = sm + 4096;    // [64][64] transposed: Ks[d][col]
    float* Vs = sm + 8192;    // [64][64] natural:    Vs[key][dh]
    float* Ps = sm + 12288;   // [64][PSTR]:          Ps[key][row]

    const int t = threadIdx.x;
    const int tx = t & 15, ty = t >> 4;
    const int qb = blockIdx.x;
    const int bh = blockIdx.y;
    const int b = bh >> 4;
    const int h = bh & 15;
    const size_t base = (size_t)bh * SS * DHH;
    const float* Qp = g_qh + base;
    const float* Kp = g_kh + base;
    const float* Vp = g_vh + base;

#pragma unroll
    for (int li = 0; li < 4; li++) {
        int f = t + li * 256;
        int row = f >> 4, c = (f & 15) * 4;
        float4 v = *(const float4*)&Qp[(size_t)(qb * 64 + row) * 64 + c];
        Qs[(c + 0) * 64 + row] = v.x;
        Qs[(c + 1) * 64 + row] = v.y;
        Qs[(c + 2) * 64 + row] = v.z;
        Qs[(c + 3) * 64 + row] = v.w;
    }

    float m_r[4], l_r[4], acc[4][4];
#pragma unroll
    for (int i = 0; i < 4; i++) {
        m_r[i] = -INFINITY;
        l_r[i] = 0.f;
#pragma unroll
        for (int j = 0; j < 4; j++) acc[i][j] = 0.f;
    }

    const float scale = 0.125f;

    for (int kb = 0; kb <= qb; kb++) {
        __syncthreads();
#pragma unroll
        for (int li = 0; li < 4; li++) {
            int f = t + li * 256;
            int row = f >> 4, c = (f & 15) * 4;
            float4 kv = *(const float4*)&Kp[(size_t)(kb * 64 + row) * 64 + c];
            Ks[(c + 0) * 64 + row] = kv.x;
            Ks[(c + 1) * 64 + row] = kv.y;
            Ks[(c + 2) * 64 + row] = kv.z;
            Ks[(c + 3) * 64 + row] = kv.w;
            float4 vv = *(const float4*)&Vp[(size_t)(kb * 64 + row) * 64 + c];
            *(float4*)&Vs[row * 64 + c] = vv;
        }
        __syncthreads();

        float s[4][4];
#pragma unroll
        for (int i = 0; i < 4; i++)
#pragma unroll
            for (int j = 0; j < 4; j++) s[i][j] = 0.f;
#pragma unroll 16
        for (int d = 0; d < 64; d++) {
            float4 qv = *(const float4*)&Qs[d * 64 + ty * 4];
            float4 kv = *(const float4*)&Ks[d * 64 + tx * 4];
            float qr[4] = {qv.x, qv.y, qv.z, qv.w};
            float kr[4] = {kv.x, kv.y, kv.z, kv.w};
#pragma unroll
            for (int i = 0; i < 4; i++)
#pragma unroll
                for (int j = 0; j < 4; j++)
                    s[i][j] = fmaf(qr[i], kr[j], s[i][j]);
        }

        const int kg0 = kb * 64 + tx * 4;
        int mk[4];
#pragma unroll
        for (int j = 0; j < 4; j++) mk[j] = mask[b * SS + kg0 + j];
#pragma unroll
        for (int j = 0; j < 4; j++) {
#pragma unroll
            for (int i = 0; i < 4; i++) {
                int ig = qb * 64 + ty * 4 + i;
                float v = s[i][j] * scale;
                if (mk[j] == 0 || (kg0 + j) > ig) v = -INFINITY;
                s[i][j] = v;
            }
        }

#pragma unroll
        for (int i = 0; i < 4; i++) {
            float rm = fmaxf(fmaxf(s[i][0], s[i][1]), fmaxf(s[i][2], s[i][3]));
#pragma unroll
            for (int off = 8; off > 0; off >>= 1)
                rm = fmaxf(rm, __shfl_xor_sync(0xffffffffu, rm, off));
            float mnew = fmaxf(m_r[i], rm);
            float scl = __expf(m_r[i] - mnew);
            float ps = 0.f;
#pragma unroll
            for (int j = 0; j < 4; j++) {
                float p = __expf(s[i][j] - mnew);
                s[i][j] = p;
                ps += p;
            }
#pragma unroll
            for (int off = 8; off > 0; off >>= 1)
                ps += __shfl_xor_sync(0xffffffffu, ps, off);
            l_r[i] = l_r[i] * scl + ps;
            m_r[i] = mnew;
#pragma unroll
            for (int j = 0; j < 4; j++) acc[i][j] *= scl;
        }

#pragma unroll
        for (int j = 0; j < 4; j++)
#pragma unroll
            for (int i = 0; i < 4; i++)
                Ps[(tx * 4 + j) * PSTR + ty * 4 + i] = s[i][j];
        __syncthreads();

#pragma unroll 8
        for (int kk = 0; kk < 64; kk++) {
            float4 vv = *(const float4*)&Vs[kk * 64 + tx * 4];
            float vr[4] = {vv.x, vv.y, vv.z, vv.w};
            float pr[4];
#pragma unroll
            for (int i = 0; i < 4; i++) pr[i] = Ps[kk * PSTR + ty * 4 + i];
#pragma unroll
            for (int i = 0; i < 4; i++)
#pragma unroll
                for (int j = 0; j < 4; j++)
                    acc[i][j] = fmaf(pr[i], vr[j], acc[i][j]);
        }
    }

#pragma unroll
    for (int i = 0; i < 4; i++) {
        float inv = 1.0f / l_r[i];
        int row = qb * 64 + ty * 4 + i;
        size_t o = ((size_t)(b * SS + row)) * DD + h * 64 + tx * 4;
        float4 w;
        w.x = acc[i][0] * inv;
        w.y = acc[i][1] * inv;
        w.z = acc[i][2] * inv;
        w.w = acc[i][3] * inv;
        *(float4*)&g_att[o] = w;
    }
}

// ---------------------------------------------------------------------------
extern "C" void kernel_launch(void* const* d_in, const int* in_sizes, int n_in,
                              void* d_out, int out_size) {
    const float* Q = (const float*)d_in[0];
    const float* K = (const float*)d_in[1];
    const float* V = (const float*)d_in[2];
    const int* mask = (const int*)d_in[3];
    const float* Wq = (const float*)d_in[4];
    const float* bq = (const float*)d_in[5];
    const float* Wk = (const float*)d_in[6];
    const float* bk = (const float*)d_in[7];
    const float* Wv = (const float*)d_in[8];
    const float* bv = (const float*)d_in[9];
    const float* Wo = (const float*)d_in[10];
    const float* bo = (const float*)d_in[11];
    float* out = (float*)d_out;

    // QKV projections into head-major scratch (TF32 tensor cores)
    dim3 gproj(DD / 128, (BB * SS) / 128, 3);
    proj_kernel<<<gproj, 256>>>(Q, K, V, Wq, bq, Wk, bk, Wv, bv);

    // Attention (dynamic smem: 3*64*64 + 64*PSTR floats = 65792 B)
    const int smem_attn = (3 * 4096 + 64 * PSTR) * (int)sizeof(float);
    cudaFuncSetAttribute(attn_kernel, cudaFuncAttributeMaxDynamicSharedMemorySize,
                         smem_attn);
    dim3 gattn(SS / 64, BB * HH);
    attn_kernel<<<gattn, 256, smem_attn>>>(mask);

    // Output projection straight into d_out (TF32 tensor cores)
    dim3 gout(DD / 128, (BB * SS) / 128);
    oproj_kernel<<<gout, 256>>>(Wo, bo, out);
}

// round 3
// speedup vs baseline: 3.1983x; 1.9755x over previous
#include <cuda_runtime.h>
#include <math.h>
#include <stdint.h>

#define BB 2
#define SS 2048
#define DD 1024
#define HH 16
#define DHH 64

// Scratch (allocation-free): head-major q/k/v and attention output
__device__ float g_qh[BB * SS * DD];
__device__ float g_kh[BB * SS * DD];
__device__ float g_vh[BB * SS * DD];
__device__ float g_att[BB * SS * DD];

// ---------------------------------------------------------------------------
// TF32 helpers
// ---------------------------------------------------------------------------
__device__ __forceinline__ uint32_t f2tf(float f) {
    uint32_t u;
    asm("cvt.rna.tf32.f32 %0, %1;" : "=r"(u) : "f"(f));
    return u;
}

__device__ __forceinline__ void mma_tf32(float* c, const uint32_t* a,
                                         const uint32_t* b) {
    asm volatile(
        "mma.sync.aligned.m16n8k8.row.col.f32.tf32.tf32.f32 "
        "{%0,%1,%2,%3}, {%4,%5,%6,%7}, {%8,%9}, {%0,%1,%2,%3};\n"
        : "+f"(c[0]), "+f"(c[1]), "+f"(c[2]), "+f"(c[3])
        : "r"(a[0]), "r"(a[1]), "r"(a[2]), "r"(a[3]), "r"(b[0]), "r"(b[1]));
}

// ---------------------------------------------------------------------------
// TF32 tensor-core GEMM: C[m][n] = sum_k A[m][k] * W[n][k] + bias[n]
// Block tile 128x128x32, 8 warps (4x2), warp tile 32x64.
// ---------------------------------------------------------------------------
template <bool HEAD_OUT>
__device__ __forceinline__ void gemm_tc(const float* __restrict__ A,
                                        const float* __restrict__ W,
                                        const float* __restrict__ bias,
                                        float* __restrict__ out) {
    __shared__ uint32_t As[128 * 36];
    __shared__ uint32_t Ws[128 * 36];
    const int t = threadIdx.x;
    const int lane = t & 31, warp = t >> 5;
    const int wm = (warp >> 1) * 32;
    const int wn = (warp & 1) * 64;
    const int g = lane >> 2, tg = lane & 3;
    const int m0 = blockIdx.y * 128, n0 = blockIdx.x * 128;

    float acc[2][8][4];
#pragma unroll
    for (int mt = 0; mt < 2; mt++)
#pragma unroll
        for (int nt = 0; nt < 8; nt++)
#pragma unroll
            for (int i = 0; i < 4; i++) acc[mt][nt][i] = 0.f;

    const int lrow = t >> 3, lcol = (t & 7) * 4;

    for (int k0 = 0; k0 < DD; k0 += 32) {
#pragma unroll
        for (int it = 0; it < 4; it++) {
            int r = lrow + it * 32;
            float4 av = *(const float4*)&A[(size_t)(m0 + r) * DD + k0 + lcol];
            uint4 au = {f2tf(av.x), f2tf(av.y), f2tf(av.z), f2tf(av.w)};
            *(uint4*)&As[r * 36 + lcol] = au;
            float4 wv = *(const float4*)&W[(size_t)(n0 + r) * DD + k0 + lcol];
            uint4 wu = {f2tf(wv.x), f2tf(wv.y), f2tf(wv.z), f2tf(wv.w)};
            *(uint4*)&Ws[r * 36 + lcol] = wu;
        }
        __syncthreads();

#pragma unroll
        for (int ks = 0; ks < 4; ks++) {
            const int kk = ks * 8;
            uint32_t a[2][4], b[8][2];
#pragma unroll
            for (int mt = 0; mt < 2; mt++) {
                int rb = wm + mt * 16 + g;
                a[mt][0] = As[rb * 36 + kk + tg];
                a[mt][1] = As[(rb + 8) * 36 + kk + tg];
                a[mt][2] = As[rb * 36 + kk + 4 + tg];
                a[mt][3] = As[(rb + 8) * 36 + kk + 4 + tg];
            }
#pragma unroll
            for (int nt = 0; nt < 8; nt++) {
                int cb = wn + nt * 8 + g;
                b[nt][0] = Ws[cb * 36 + kk + tg];
                b[nt][1] = Ws[cb * 36 + kk + 4 + tg];
            }
#pragma unroll
            for (int mt = 0; mt < 2; mt++)
#pragma unroll
                for (int nt = 0; nt < 8; nt++)
                    mma_tf32(acc[mt][nt], a[mt], b[nt]);
        }
        __syncthreads();
    }

#pragma unroll
    for (int mt = 0; mt < 2; mt++) {
#pragma unroll
        for (int i = 0; i < 2; i++) {
            int m = m0 + wm + mt * 16 + g + i * 8;
#pragma unroll
            for (int nt = 0; nt < 8; nt++) {
                int n = n0 + wn + nt * 8 + tg * 2;
                float2 v;
                v.x = acc[mt][nt][i * 2 + 0] + bias[n];
                v.y = acc[mt][nt][i * 2 + 1] + bias[n + 1];
                if (HEAD_OUT) {
                    int bI = m >> 11, s = m & (SS - 1);
                    int h = n >> 6, dh = n & 63;
                    *(float2*)&out[(((size_t)(bI * HH + h) * SS + s) << 6) + dh] = v;
                } else {
                    *(float2*)&out[(size_t)m * DD + n] = v;
                }
            }
        }
    }
}

__global__ void __launch_bounds__(256) proj_kernel(
    const float* __restrict__ Q, const float* __restrict__ K,
    const float* __restrict__ V, const float* __restrict__ Wq,
    const float* __restrict__ bq, const float* __restrict__ Wk,
    const float* __restrict__ bk, const float* __restrict__ Wv,
    const float* __restrict__ bv) {
    int z = blockIdx.z;
    const float* A = (z == 0) ? Q : (z == 1) ? K : V;
    const float* W = (z == 0) ? Wq : (z == 1) ? Wk : Wv;
    const float* bias = (z == 0) ? bq : (z == 1) ? bk : bv;
    float* out = (z == 0) ? g_qh : (z == 1) ? g_kh : g_vh;
    gemm_tc<true>(A, W, bias, out);
}

__global__ void __launch_bounds__(256) oproj_kernel(const float* __restrict__ Wo,
                                                    const float* __restrict__ bo,
                                                    float* __restrict__ out) {
    gemm_tc<false>(g_att, Wo, bo, out);
}

// ---------------------------------------------------------------------------
// Tensor-core flash attention. Grid (S/64, B*H), 128 threads (4 warps).
// Warp w owns query rows [qb*64 + w*16, +16). QK^T and P*V via tf32 mma.
// sK (stride 72): K tile [key][d]; reused as Ps [qrow][key] after QK.
// sV (stride 72): V tile [key][d] natural (B-frag for PV reads it directly).
// ---------------------------------------------------------------------------
#define AST 72
__global__ void __launch_bounds__(128) attn_kernel(const int* __restrict__ mask) {
    __shared__ uint32_t sK[64 * AST];
    __shared__ uint32_t sV[64 * AST];

    const int t = threadIdx.x;
    const int lane = t & 31, w = t >> 5;
    const int g = lane >> 2, tg = lane & 3;
    const int qb = blockIdx.x;
    const int bh = blockIdx.y;
    const int b = bh >> 4, h = bh & 15;
    const size_t base = (size_t)bh * SS * DHH;
    const float* Qp = g_qh + base;
    const float* Kp = g_kh + base;
    const float* Vp = g_vh + base;

    // Stage Q tile through sK, pull warp's A-fragments into registers.
#pragma unroll
    for (int i = 0; i < 8; i++) {
        int f = t + i * 128;
        int r = f >> 4, c = (f & 15) * 4;
        float4 v = *(const float4*)&Qp[(size_t)(qb * 64 + r) * 64 + c];
        uint4 u = {f2tf(v.x), f2tf(v.y), f2tf(v.z), f2tf(v.w)};
        *(uint4*)&sK[r * AST + c] = u;
    }
    __syncthreads();
    uint32_t aq[8][4];
    {
        const int r0 = (w * 16 + g) * AST, r1 = (w * 16 + g + 8) * AST;
#pragma unroll
        for (int ks = 0; ks < 8; ks++) {
            aq[ks][0] = sK[r0 + ks * 8 + tg];
            aq[ks][1] = sK[r1 + ks * 8 + tg];
            aq[ks][2] = sK[r0 + ks * 8 + 4 + tg];
            aq[ks][3] = sK[r1 + ks * 8 + 4 + tg];
        }
    }

    float m0 = -INFINITY, m1 = -INFINITY, l0 = 0.f, l1 = 0.f;
    float o[8][4];
#pragma unroll
    for (int nt = 0; nt < 8; nt++)
#pragma unroll
        for (int i = 0; i < 4; i++) o[nt][i] = 0.f;

    const float scale = 0.125f;  // 1/sqrt(64)
    const int row0g = qb * 64 + w * 16 + g;

    for (int kb = 0; kb <= qb; kb++) {
        __syncthreads();  // prior iter's Ps/Vs reads done
        // Stage K and V (tf32) — both natural [key][d], stride AST.
#pragma unroll
        for (int i = 0; i < 8; i++) {
            int f = t + i * 128;
            int r = f >> 4, c = (f & 15) * 4;
            float4 kv = *(const float4*)&Kp[(size_t)(kb * 64 + r) * 64 + c];
            uint4 ku = {f2tf(kv.x), f2tf(kv.y), f2tf(kv.z), f2tf(kv.w)};
            *(uint4*)&sK[r * AST + c] = ku;
            float4 vv = *(const float4*)&Vp[(size_t)(kb * 64 + r) * 64 + c];
            uint4 vu = {f2tf(vv.x), f2tf(vv.y), f2tf(vv.z), f2tf(vv.w)};
            *(uint4*)&sV[r * AST + c] = vu;
        }
        __syncthreads();

        // QK^T: scores c_[nt] covers keys nt*8..nt*8+7
        float c_[8][4];
#pragma unroll
        for (int nt = 0; nt < 8; nt++)
#pragma unroll
            for (int i = 0; i < 4; i++) c_[nt][i] = 0.f;
#pragma unroll
        for (int ks = 0; ks < 8; ks++) {
            uint32_t bf[8][2];
#pragma unroll
            for (int nt = 0; nt < 8; nt++) {
                int cb = (nt * 8 + g) * AST;
                bf[nt][0] = sK[cb + ks * 8 + tg];
                bf[nt][1] = sK[cb + ks * 8 + 4 + tg];
            }
#pragma unroll
            for (int nt = 0; nt < 8; nt++) mma_tf32(c_[nt], aq[ks], bf[nt]);
        }
        __syncthreads();  // everyone done reading sK before Ps overwrite

        // Scale + padding/causal mask
        const int colb = kb * 64 + tg * 2;
#pragma unroll
        for (int nt = 0; nt < 8; nt++) {
            int col = colb + nt * 8;
            int mk0 = __ldg(&mask[b * SS + col]);
            int mk1 = __ldg(&mask[b * SS + col + 1]);
#pragma unroll
            for (int hh = 0; hh < 2; hh++) {
                int row = row0g + hh * 8;
                float v0 = c_[nt][hh * 2] * scale;
                float v1 = c_[nt][hh * 2 + 1] * scale;
                if (mk0 == 0 || (kb == qb && col > row)) v0 = -INFINITY;
                if (mk1 == 0 || (kb == qb && col + 1 > row)) v1 = -INFINITY;
                c_[nt][hh * 2] = v0;
                c_[nt][hh * 2 + 1] = v1;
            }
        }

        // Online softmax per row half (rows g and g+8)
#pragma unroll
        for (int hh = 0; hh < 2; hh++) {
            float mprev = hh ? m1 : m0;
            float rm = -INFINITY;
#pragma unroll
            for (int nt = 0; nt < 8; nt++)
                rm = fmaxf(rm, fmaxf(c_[nt][hh * 2], c_[nt][hh * 2 + 1]));
            rm = fmaxf(rm, __shfl_xor_sync(0xffffffffu, rm, 1));
            rm = fmaxf(rm, __shfl_xor_sync(0xffffffffu, rm, 2));
            float mn = fmaxf(mprev, rm);
            float scl = __expf(mprev - mn);
            float ps = 0.f;
#pragma unroll
            for (int nt = 0; nt < 8; nt++) {
                float p0 = __expf(c_[nt][hh * 2] - mn);
                float p1 = __expf(c_[nt][hh * 2 + 1] - mn);
                c_[nt][hh * 2] = p0;
                c_[nt][hh * 2 + 1] = p1;
                ps += p0 + p1;
            }
            ps += __shfl_xor_sync(0xffffffffu, ps, 1);
            ps += __shfl_xor_sync(0xffffffffu, ps, 2);
            if (hh) {
                l1 = l1 * scl + ps;
                m1 = mn;
            } else {
                l0 = l0 * scl + ps;
                m0 = mn;
            }
#pragma unroll
            for (int nt = 0; nt < 8; nt++) {
                o[nt][hh * 2] *= scl;
                o[nt][hh * 2 + 1] *= scl;
            }
        }

        // Store P (tf32) into sK as Ps[qrow][key] — warp-private rows
        {
            const int r0 = (w * 16 + g) * AST, r1 = (w * 16 + g + 8) * AST;
#pragma unroll
            for (int nt = 0; nt < 8; nt++) {
                uint2 u0 = {f2tf(c_[nt][0]), f2tf(c_[nt][1])};
                *(uint2*)&sK[r0 + nt * 8 + tg * 2] = u0;
                uint2 u1 = {f2tf(c_[nt][2]), f2tf(c_[nt][3])};
                *(uint2*)&sK[r1 + nt * 8 + tg * 2] = u1;
            }
        }
        __syncwarp();

        // P * V: A = Ps (warp rows), B = V natural [key][d]
        {
            const int r0 = (w * 16 + g) * AST, r1 = (w * 16 + g + 8) * AST;
#pragma unroll
            for (int kk = 0; kk < 8; kk++) {
                uint32_t ap[4];
                ap[0] = sK[r0 + kk * 8 + tg];
                ap[1] = sK[r1 + kk * 8 + tg];
                ap[2] = sK[r0 + kk * 8 + 4 + tg];
                ap[3] = sK[r1 + kk * 8 + 4 + tg];
                uint32_t bv[8][2];
#pragma unroll
                for (int nt = 0; nt < 8; nt++) {
                    bv[nt][0] = sV[(kk * 8 + tg) * AST + nt * 8 + g];
                    bv[nt][1] = sV[(kk * 8 + tg + 4) * AST + nt * 8 + g];
                }
#pragma unroll
                for (int nt = 0; nt < 8; nt++) mma_tf32(o[nt], ap, bv[nt]);
            }
        }
    }

    // Epilogue: normalize and write [B,S,D] for output projection
    float inv0 = 1.f / l0, inv1 = 1.f / l1;
#pragma unroll
    for (int nt = 0; nt < 8; nt++) {
        int d = h * 64 + nt * 8 + tg * 2;
        float2 v0 = {o[nt][0] * inv0, o[nt][1] * inv0};
        *(float2*)&g_att[(size_t)(b * SS + row0g) * DD + d] = v0;
        float2 v1 = {o[nt][2] * inv1, o[nt][3] * inv1};
        *(float2*)&g_att[(size_t)(b * SS + row0g + 8) * DD + d] = v1;
    }
}

// ---------------------------------------------------------------------------
extern "C" void kernel_launch(void* const* d_in, const int* in_sizes, int n_in,
                              void* d_out, int out_size) {
    const float* Q = (const float*)d_in[0];
    const float* K = (const float*)d_in[1];
    const float* V = (const float*)d_in[2];
    const int* mask = (const int*)d_in[3];
    const float* Wq = (const float*)d_in[4];
    const float* bq = (const float*)d_in[5];
    const float* Wk = (const float*)d_in[6];
    const float* bk = (const float*)d_in[7];
    const float* Wv = (const float*)d_in[8];
    const float* bv = (const float*)d_in[9];
    const float* Wo = (const float*)d_in[10];
    const float* bo = (const float*)d_in[11];
    float* out = (float*)d_out;

    dim3 gproj(DD / 128, (BB * SS) / 128, 3);
    proj_kernel<<<gproj, 256>>>(Q, K, V, Wq, bq, Wk, bk, Wv, bv);

    dim3 gattn(SS / 64, BB * HH);
    attn_kernel<<<gattn, 128>>>(mask);

    dim3 gout(DD / 128, (BB * SS) / 128);
    oproj_kernel<<<gout, 256>>>(Wo, bo, out);
}

// round 4
// speedup vs baseline: 3.4316x; 1.0729x over previous
#include <cuda_runtime.h>
#include <math.h>
#include <stdint.h>

#define BB 2
#define SS 2048
#define DD 1024
#define HH 16
#define DHH 64

// Scratch (allocation-free): head-major q/k/v (pre-rounded to tf32 values)
__device__ float g_qh[BB * SS * DD];
__device__ float g_kh[BB * SS * DD];
__device__ float g_vh[BB * SS * DD];
__device__ float g_att[BB * SS * DD];

// ---------------------------------------------------------------------------
// Helpers
// ---------------------------------------------------------------------------
__device__ __forceinline__ uint32_t f2tf(float f) {
    uint32_t u;
    asm("cvt.rna.tf32.f32 %0, %1;" : "=r"(u) : "f"(f));
    return u;
}

__device__ __forceinline__ void mma_tf32(float* c, const uint32_t* a,
                                         const uint32_t* b) {
    asm volatile(
        "mma.sync.aligned.m16n8k8.row.col.f32.tf32.tf32.f32 "
        "{%0,%1,%2,%3}, {%4,%5,%6,%7}, {%8,%9}, {%0,%1,%2,%3};\n"
        : "+f"(c[0]), "+f"(c[1]), "+f"(c[2]), "+f"(c[3])
        : "r"(a[0]), "r"(a[1]), "r"(a[2]), "r"(a[3]), "r"(b[0]), "r"(b[1]));
}

__device__ __forceinline__ void cp16(void* sdst, const void* gsrc) {
    uint32_t a = (uint32_t)__cvta_generic_to_shared(sdst);
    asm volatile("cp.async.cg.shared.global [%0], [%1], 16;" ::"r"(a),
                     "l"(gsrc));
}
#define CP_COMMIT() asm volatile("cp.async.commit_group;")
#define CP_WAIT0() asm volatile("cp.async.wait_group 0;" ::: "memory")

// ---------------------------------------------------------------------------
// TF32 GEMM, cp.async 2-stage pipeline. C[m][n] = sum_k A[m][k]*W[n][k]+b[n]
// Block 128x128x32, 8 warps, warp tile 32x64. Smem stride 36 (conflict-free).
// ROUND_OUT: round outputs to tf32 values (for q/k/v scratch).
// ---------------------------------------------------------------------------
#define GST 36
#define GSTAGE (2 * 128 * GST)  // floats per stage (A + W)

template <bool HEAD_OUT, bool ROUND_OUT>
__device__ __forceinline__ void gemm_tc(const float* __restrict__ A,
                                        const float* __restrict__ W,
                                        const float* __restrict__ bias,
                                        float* __restrict__ out) {
    extern __shared__ float sm[];
    const int t = threadIdx.x;
    const int lane = t & 31, warp = t >> 5;
    const int wm = (warp >> 1) * 32;
    const int wn = (warp & 1) * 64;
    const int g = lane >> 2, tg = lane & 3;
    const int m0 = blockIdx.y * 128, n0 = blockIdx.x * 128;
    const int lrow = t >> 3, lcol = (t & 7) * 4;

    float acc[2][8][4];
#pragma unroll
    for (int mt = 0; mt < 2; mt++)
#pragma unroll
        for (int nt = 0; nt < 8; nt++)
#pragma unroll
            for (int i = 0; i < 4; i++) acc[mt][nt][i] = 0.f;

    // stage copy: 4 A rows + 4 W rows per thread, 16B each
    auto stage = [&](int buf, int k0) {
        float* As = sm + buf * GSTAGE;
        float* Ws = As + 128 * GST;
#pragma unroll
        for (int it = 0; it < 4; it++) {
            int r = lrow + it * 32;
            cp16(&As[r * GST + lcol], &A[(size_t)(m0 + r) * DD + k0 + lcol]);
            cp16(&Ws[r * GST + lcol], &W[(size_t)(n0 + r) * DD + k0 + lcol]);
        }
        CP_COMMIT();
    };

    stage(0, 0);

    for (int it = 0; it < DD / 32; it++) {
        const int buf = it & 1;
        CP_WAIT0();
        __syncthreads();
        if (it + 1 < DD / 32) stage(buf ^ 1, (it + 1) * 32);

        const float* As = sm + buf * GSTAGE;
        const float* Ws = As + 128 * GST;
#pragma unroll
        for (int ks = 0; ks < 4; ks++) {
            const int kk = ks * 8;
            uint32_t a[2][4], b[8][2];
#pragma unroll
            for (int mt = 0; mt < 2; mt++) {
                int rb = wm + mt * 16 + g;
                a[mt][0] = f2tf(As[rb * GST + kk + tg]);
                a[mt][1] = f2tf(As[(rb + 8) * GST + kk + tg]);
                a[mt][2] = f2tf(As[rb * GST + kk + 4 + tg]);
                a[mt][3] = f2tf(As[(rb + 8) * GST + kk + 4 + tg]);
            }
#pragma unroll
            for (int nt = 0; nt < 8; nt++) {
                int cb = wn + nt * 8 + g;
                b[nt][0] = f2tf(Ws[cb * GST + kk + tg]);
                b[nt][1] = f2tf(Ws[cb * GST + kk + 4 + tg]);
            }
#pragma unroll
            for (int mt = 0; mt < 2; mt++)
#pragma unroll
                for (int nt = 0; nt < 8; nt++)
                    mma_tf32(acc[mt][nt], a[mt], b[nt]);
        }
        __syncthreads();
    }

#pragma unroll
    for (int mt = 0; mt < 2; mt++) {
#pragma unroll
        for (int i = 0; i < 2; i++) {
            int m = m0 + wm + mt * 16 + g + i * 8;
#pragma unroll
            for (int nt = 0; nt < 8; nt++) {
                int n = n0 + wn + nt * 8 + tg * 2;
                float vx = acc[mt][nt][i * 2 + 0] + bias[n];
                float vy = acc[mt][nt][i * 2 + 1] + bias[n + 1];
                float2 v;
                if (ROUND_OUT) {
                    v.x = __uint_as_float(f2tf(vx));
                    v.y = __uint_as_float(f2tf(vy));
                } else {
                    v.x = vx;
                    v.y = vy;
                }
                if (HEAD_OUT) {
                    int bI = m >> 11, s = m & (SS - 1);
                    int h = n >> 6, dh = n & 63;
                    *(float2*)&out[(((size_t)(bI * HH + h) * SS + s) << 6) + dh] = v;
                } else {
                    *(float2*)&out[(size_t)m * DD + n] = v;
                }
            }
        }
    }
}

__global__ void __launch_bounds__(256) proj_kernel(
    const float* __restrict__ Q, const float* __restrict__ K,
    const float* __restrict__ V, const float* __restrict__ Wq,
    const float* __restrict__ bq, const float* __restrict__ Wk,
    const float* __restrict__ bk, const float* __restrict__ Wv,
    const float* __restrict__ bv) {
    int z = blockIdx.z;
    const float* A = (z == 0) ? Q : (z == 1) ? K : V;
    const float* W = (z == 0) ? Wq : (z == 1) ? Wk : Wv;
    const float* bias = (z == 0) ? bq : (z == 1) ? bk : bv;
    float* out = (z == 0) ? g_qh : (z == 1) ? g_kh : g_vh;
    gemm_tc<true, true>(A, W, bias, out);
}

__global__ void __launch_bounds__(256) oproj_kernel(const float* __restrict__ Wo,
                                                    const float* __restrict__ bo,
                                                    float* __restrict__ out) {
    gemm_tc<false, false>(g_att, Wo, bo, out);
}

// ---------------------------------------------------------------------------
// Tensor-core flash attention, cp.async double-buffered K/V.
// Grid (S/64, B*H), 128 threads (4 warps), warp w owns 16 query rows.
// Scratch q/k/v hold tf32-valued floats (pre-rounded by proj) -> no cvt here.
// Strides: K/P buffers 68 (banks 4g+tg, bijective), V buffers 72 (8tg+g).
// ---------------------------------------------------------------------------
#define KST 68
#define VST 72
#define PST 68
#define OFF_K0 0
#define OFF_K1 (64 * KST)
#define OFF_V0 (2 * 64 * KST)
#define OFF_V1 (2 * 64 * KST + 64 * VST)
#define OFF_P (2 * 64 * KST + 2 * 64 * VST)
#define ATT_SMEM ((2 * 64 * KST + 2 * 64 * VST + 64 * PST) * 4)

__global__ void __launch_bounds__(128) attn_kernel(const int* __restrict__ mask) {
    extern __shared__ uint32_t smu[];
    const int t = threadIdx.x;
    const int lane = t & 31, w = t >> 5;
    const int g = lane >> 2, tg = lane & 3;
    const int qb = blockIdx.x;
    const int bh = blockIdx.y;
    const int b = bh >> 4, h = bh & 15;
    const size_t base = (size_t)bh * SS * DHH;
    const float* Qp = g_qh + base;
    const float* Kp = g_kh + base;
    const float* Vp = g_vh + base;

    const int lr = t >> 4, lc = (t & 15) * 4;  // staging coords (8 iters)

    // Issue cp.async for kb=0 K/V immediately
    auto stageKV = [&](int buf, int kb) {
        uint32_t* sK = smu + (buf ? OFF_K1 : OFF_K0);
        uint32_t* sV = smu + (buf ? OFF_V1 : OFF_V0);
#pragma unroll
        for (int i = 0; i < 8; i++) {
            int r = lr + i * 8;
            cp16(&sK[r * KST + lc], &Kp[(size_t)(kb * 64 + r) * 64 + lc]);
            cp16(&sV[r * VST + lc], &Vp[(size_t)(kb * 64 + r) * 64 + lc]);
        }
        CP_COMMIT();
    };
    stageKV(0, 0);

    // Stage Q through sP (plain), then pull warp A-fragments to registers
    uint32_t* sP = smu + OFF_P;
#pragma unroll
    for (int i = 0; i < 8; i++) {
        int r = lr + i * 8;
        *(float4*)&sP[r * PST + lc] = *(const float4*)&Qp[(size_t)(qb * 64 + r) * 64 + lc];
    }
    __syncthreads();
    uint32_t aq[8][4];
    {
        const int r0 = (w * 16 + g) * PST, r1 = (w * 16 + g + 8) * PST;
#pragma unroll
        for (int ks = 0; ks < 8; ks++) {
            aq[ks][0] = sP[r0 + ks * 8 + tg];
            aq[ks][1] = sP[r1 + ks * 8 + tg];
            aq[ks][2] = sP[r0 + ks * 8 + 4 + tg];
            aq[ks][3] = sP[r1 + ks * 8 + 4 + tg];
        }
    }
    __syncthreads();  // done reading Q from sP before P overwrites

    float m0 = -INFINITY, m1 = -INFINITY, l0 = 0.f, l1 = 0.f;
    float o[8][4];
#pragma unroll
    for (int nt = 0; nt < 8; nt++)
#pragma unroll
        for (int i = 0; i < 4; i++) o[nt][i] = 0.f;

    const float scale = 0.125f;  // 1/sqrt(64)
    const int row0g = qb * 64 + w * 16 + g;

    for (int kb = 0; kb <= qb; kb++) {
        const int buf = kb & 1;
        CP_WAIT0();
        __syncthreads();  // K/V[buf] visible; prior iter reads of buf^1 done
        if (kb < qb) stageKV(buf ^ 1, kb + 1);

        const uint32_t* sK = smu + (buf ? OFF_K1 : OFF_K0);
        const uint32_t* sV = smu + (buf ? OFF_V1 : OFF_V0);

        // QK^T
        float c_[8][4];
#pragma unroll
        for (int nt = 0; nt < 8; nt++)
#pragma unroll
            for (int i = 0; i < 4; i++) c_[nt][i] = 0.f;
#pragma unroll
        for (int ks = 0; ks < 8; ks++) {
            uint32_t bf[8][2];
#pragma unroll
            for (int nt = 0; nt < 8; nt++) {
                int cb = (nt * 8 + g) * KST;
                bf[nt][0] = sK[cb + ks * 8 + tg];
                bf[nt][1] = sK[cb + ks * 8 + 4 + tg];
            }
#pragma unroll
            for (int nt = 0; nt < 8; nt++) mma_tf32(c_[nt], aq[ks], bf[nt]);
        }

        // Scale + padding/causal mask
        const int colb = kb * 64 + tg * 2;
#pragma unroll
        for (int nt = 0; nt < 8; nt++) {
            int col = colb + nt * 8;
            int mk0 = __ldg(&mask[b * SS + col]);
            int mk1 = __ldg(&mask[b * SS + col + 1]);
#pragma unroll
            for (int hh = 0; hh < 2; hh++) {
                int row = row0g + hh * 8;
                float v0 = c_[nt][hh * 2] * scale;
                float v1 = c_[nt][hh * 2 + 1] * scale;
                if (mk0 == 0 || (kb == qb && col > row)) v0 = -INFINITY;
                if (mk1 == 0 || (kb == qb && col + 1 > row)) v1 = -INFINITY;
                c_[nt][hh * 2] = v0;
                c_[nt][hh * 2 + 1] = v1;
            }
        }

        // Online softmax per row half (rows g and g+8)
#pragma unroll
        for (int hh = 0; hh < 2; hh++) {
            float mprev = hh ? m1 : m0;
            float rm = -INFINITY;
#pragma unroll
            for (int nt = 0; nt < 8; nt++)
                rm = fmaxf(rm, fmaxf(c_[nt][hh * 2], c_[nt][hh * 2 + 1]));
            rm = fmaxf(rm, __shfl_xor_sync(0xffffffffu, rm, 1));
            rm = fmaxf(rm, __shfl_xor_sync(0xffffffffu, rm, 2));
            float mn = fmaxf(mprev, rm);
            float scl = __expf(mprev - mn);
            float ps = 0.f;
#pragma unroll
            for (int nt = 0; nt < 8; nt++) {
                float p0 = __expf(c_[nt][hh * 2] - mn);
                float p1 = __expf(c_[nt][hh * 2 + 1] - mn);
                c_[nt][hh * 2] = p0;
                c_[nt][hh * 2 + 1] = p1;
                ps += p0 + p1;
            }
            ps += __shfl_xor_sync(0xffffffffu, ps, 1);
            ps += __shfl_xor_sync(0xffffffffu, ps, 2);
            if (hh) {
                l1 = l1 * scl + ps;
                m1 = mn;
            } else {
                l0 = l0 * scl + ps;
                m0 = mn;
            }
#pragma unroll
            for (int nt = 0; nt < 8; nt++) {
                o[nt][hh * 2] *= scl;
                o[nt][hh * 2 + 1] *= scl;
            }
        }

        // Store P (tf32) into warp-private sP rows
        {
            const int r0 = (w * 16 + g) * PST, r1 = (w * 16 + g + 8) * PST;
#pragma unroll
            for (int nt = 0; nt < 8; nt++) {
                uint2 u0 = {f2tf(c_[nt][0]), f2tf(c_[nt][1])};
                *(uint2*)&sP[r0 + nt * 8 + tg * 2] = u0;
                uint2 u1 = {f2tf(c_[nt][2]), f2tf(c_[nt][3])};
                *(uint2*)&sP[r1 + nt * 8 + tg * 2] = u1;
            }
        }
        __syncwarp();

        // P * V
        {
            const int r0 = (w * 16 + g) * PST, r1 = (w * 16 + g + 8) * PST;
#pragma unroll
            for (int kk = 0; kk < 8; kk++) {
                uint32_t ap[4];
                ap[0] = sP[r0 + kk * 8 + tg];
                ap[1] = sP[r1 + kk * 8 + tg];
                ap[2] = sP[r0 + kk * 8 + 4 + tg];
                ap[3] = sP[r1 + kk * 8 + 4 + tg];
                uint32_t bv[8][2];
#pragma unroll
                for (int nt = 0; nt < 8; nt++) {
                    bv[nt][0] = sV[(kk * 8 + tg) * VST + nt * 8 + g];
                    bv[nt][1] = sV[(kk * 8 + tg + 4) * VST + nt * 8 + g];
                }
#pragma unroll
                for (int nt = 0; nt < 8; nt++) mma_tf32(o[nt], ap, bv[nt]);
            }
        }
    }

    // Epilogue: normalize, write [B,S,D]
    float inv0 = 1.f / l0, inv1 = 1.f / l1;
#pragma unroll
    for (int nt = 0; nt < 8; nt++) {
        int d = h * 64 + nt * 8 + tg * 2;
        float2 v0 = {o[nt][0] * inv0, o[nt][1] * inv0};
        *(float2*)&g_att[(size_t)(b * SS + row0g) * DD + d] = v0;
        float2 v1 = {o[nt][2] * inv1, o[nt][3] * inv1};
        *(float2*)&g_att[(size_t)(b * SS + row0g + 8) * DD + d] = v1;
    }
}

// ---------------------------------------------------------------------------
extern "C" void kernel_launch(void* const* d_in, const int* in_sizes, int n_in,
                              void* d_out, int out_size) {
    const float* Q = (const float*)d_in[0];
    const float* K = (const float*)d_in[1];
    const float* V = (const float*)d_in[2];
    const int* mask = (const int*)d_in[3];
    const float* Wq = (const float*)d_in[4];
    const float* bq = (const float*)d_in[5];
    const float* Wk = (const float*)d_in[6];
    const float* bk = (const float*)d_in[7];
    const float* Wv = (const float*)d_in[8];
    const float* bv = (const float*)d_in[9];
    const float* Wo = (const float*)d_in[10];
    const float* bo = (const float*)d_in[11];
    float* out = (float*)d_out;

    const int gemm_smem = 2 * GSTAGE * (int)sizeof(float);  // 73728 B
    static int configured = 0;
    if (!configured) {
        cudaFuncSetAttribute(proj_kernel, cudaFuncAttributeMaxDynamicSharedMemorySize,
                             gemm_smem);
        cudaFuncSetAttribute(oproj_kernel, cudaFuncAttributeMaxDynamicSharedMemorySize,
                             gemm_smem);
        cudaFuncSetAttribute(attn_kernel, cudaFuncAttributeMaxDynamicSharedMemorySize,
                             ATT_SMEM);
        configured = 1;
    }

    dim3 gproj(DD / 128, (BB * SS) / 128, 3);
    proj_kernel<<<gproj, 256, gemm_smem>>>(Q, K, V, Wq, bq, Wk, bk, Wv, bv);

    dim3 gattn(SS / 64, BB * HH);
    attn_kernel<<<gattn, 128, ATT_SMEM>>>(mask);

    dim3 gout(DD / 128, (BB * SS) / 128);
    oproj_kernel<<<gout, 256, gemm_smem>>>(Wo, bo, out);
}

// round 5
// speedup vs baseline: 3.6552x; 1.0651x over previous
#include <cuda_runtime.h>
#include <math.h>
#include <stdint.h>

#define BB 2
#define SS 2048
#define DD 1024
#define HH 16
#define DHH 64
#define NQ (BB * SS * DD)
#define NW (DD * DD)

// Scratch (allocation-free)
__device__ float g_qh[NQ];   // head-major q (tf32-valued)
__device__ float g_kh[NQ];   // head-major k
__device__ float g_vh[NQ];   // head-major v
__device__ float g_att[NQ];  // attention out (tf32-valued)
__device__ float g_qr[NQ];   // rounded inputs
__device__ float g_kr[NQ];
__device__ float g_vr[NQ];
__device__ float g_wq[NW];   // rounded weights
__device__ float g_wk[NW];
__device__ float g_wv[NW];
__device__ float g_wo[NW];

// ---------------------------------------------------------------------------
__device__ __forceinline__ uint32_t f2tf(float f) {
    uint32_t u;
    asm("cvt.rna.tf32.f32 %0, %1;" : "=r"(u) : "f"(f));
    return u;
}

__device__ __forceinline__ void mma_tf32(float* c, const uint32_t* a,
                                         const uint32_t* b) {
    asm volatile(
        "mma.sync.aligned.m16n8k8.row.col.f32.tf32.tf32.f32 "
        "{%0,%1,%2,%3}, {%4,%5,%6,%7}, {%8,%9}, {%0,%1,%2,%3};\n"
        : "+f"(c[0]), "+f"(c[1]), "+f"(c[2]), "+f"(c[3])
        : "r"(a[0]), "r"(a[1]), "r"(a[2]), "r"(a[3]), "r"(b[0]), "r"(b[1]));
}

__device__ __forceinline__ void cp16(void* sdst, const void* gsrc) {
    uint32_t a = (uint32_t)__cvta_generic_to_shared(sdst);
    asm volatile("cp.async.cg.shared.global [%0], [%1], 16;" ::"r"(a),
                     "l"(gsrc));
}
#define CP_COMMIT() asm volatile("cp.async.commit_group;")
#define CP_WAIT0() asm volatile("cp.async.wait_group 0;" ::: "memory")

// ---------------------------------------------------------------------------
// Pre-round all GEMM operands to tf32 values. z selects tensor.
// ---------------------------------------------------------------------------
__global__ void round_kernel(const float* __restrict__ Q,
                             const float* __restrict__ K,
                             const float* __restrict__ V,
                             const float* __restrict__ Wq,
                             const float* __restrict__ Wk,
                             const float* __restrict__ Wv,
                             const float* __restrict__ Wo) {
    const int z = blockIdx.z;
    const float* src;
    float* dst;
    int n4;
    switch (z) {
        case 0: src = Q;  dst = g_qr; n4 = NQ / 4; break;
        case 1: src = K;  dst = g_kr; n4 = NQ / 4; break;
        case 2: src = V;  dst = g_vr; n4 = NQ / 4; break;
        case 3: src = Wq; dst = g_wq; n4 = NW / 4; break;
        case 4: src = Wk; dst = g_wk; n4 = NW / 4; break;
        case 5: src = Wv; dst = g_wv; n4 = NW / 4; break;
        default: src = Wo; dst = g_wo; n4 = NW / 4; break;
    }
    const int stride = gridDim.x * blockDim.x;
    for (int i = blockIdx.x * blockDim.x + threadIdx.x; i < n4; i += stride) {
        float4 v = ((const float4*)src)[i];
        v.x = __uint_as_float(f2tf(v.x));
        v.y = __uint_as_float(f2tf(v.y));
        v.z = __uint_as_float(f2tf(v.z));
        v.w = __uint_as_float(f2tf(v.w));
        ((float4*)dst)[i] = v;
    }
}

// ---------------------------------------------------------------------------
// TF32 GEMM, cp.async 2-stage pipeline, NO cvt in inner loop (pre-rounded).
// Block 128x128x32, 4 warps, warp tile 64x64. Smem stride 36 (conflict-free).
// ---------------------------------------------------------------------------
#define GST 36
#define GSTAGE (2 * 128 * GST)  // floats per stage (A + W)

template <bool HEAD_OUT, bool ROUND_OUT>
__device__ __forceinline__ void gemm_tc(const float* __restrict__ A,
                                        const float* __restrict__ W,
                                        const float* __restrict__ bias,
                                        float* __restrict__ out) {
    extern __shared__ float sm[];
    const int t = threadIdx.x;  // 128 threads
    const int lane = t & 31, warp = t >> 5;
    const int wm = (warp >> 1) * 64;
    const int wn = (warp & 1) * 64;
    const int g = lane >> 2, tg = lane & 3;
    const int m0 = blockIdx.y * 128, n0 = blockIdx.x * 128;
    const int lrow = t >> 3, lcol = (t & 7) * 4;

    float acc[4][8][4];
#pragma unroll
    for (int mt = 0; mt < 4; mt++)
#pragma unroll
        for (int nt = 0; nt < 8; nt++)
#pragma unroll
            for (int i = 0; i < 4; i++) acc[mt][nt][i] = 0.f;

    // stage copy: 8 A rows + 8 W rows per thread, 16B each
    auto stage = [&](int buf, int k0) {
        float* As = sm + buf * GSTAGE;
        float* Ws = As + 128 * GST;
#pragma unroll
        for (int it = 0; it < 8; it++) {
            int r = lrow + it * 16;
            cp16(&As[r * GST + lcol], &A[(size_t)(m0 + r) * DD + k0 + lcol]);
            cp16(&Ws[r * GST + lcol], &W[(size_t)(n0 + r) * DD + k0 + lcol]);
        }
        CP_COMMIT();
    };

    stage(0, 0);

    for (int it = 0; it < DD / 32; it++) {
        const int buf = it & 1;
        CP_WAIT0();
        __syncthreads();
        if (it + 1 < DD / 32) stage(buf ^ 1, (it + 1) * 32);

        const float* As = sm + buf * GSTAGE;
        const float* Ws = As + 128 * GST;
#pragma unroll
        for (int ks = 0; ks < 4; ks++) {
            const int kk = ks * 8;
            uint32_t a[4][4], b[8][2];
#pragma unroll
            for (int mt = 0; mt < 4; mt++) {
                int rb = wm + mt * 16 + g;
                a[mt][0] = __float_as_uint(As[rb * GST + kk + tg]);
                a[mt][1] = __float_as_uint(As[(rb + 8) * GST + kk + tg]);
                a[mt][2] = __float_as_uint(As[rb * GST + kk + 4 + tg]);
                a[mt][3] = __float_as_uint(As[(rb + 8) * GST + kk + 4 + tg]);
            }
#pragma unroll
            for (int nt = 0; nt < 8; nt++) {
                int cb = wn + nt * 8 + g;
                b[nt][0] = __float_as_uint(Ws[cb * GST + kk + tg]);
                b[nt][1] = __float_as_uint(Ws[cb * GST + kk + 4 + tg]);
            }
#pragma unroll
            for (int mt = 0; mt < 4; mt++)
#pragma unroll
                for (int nt = 0; nt < 8; nt++)
                    mma_tf32(acc[mt][nt], a[mt], b[nt]);
        }
        __syncthreads();
    }

#pragma unroll
    for (int mt = 0; mt < 4; mt++) {
#pragma unroll
        for (int i = 0; i < 2; i++) {
            int m = m0 + wm + mt * 16 + g + i * 8;
#pragma unroll
            for (int nt = 0; nt < 8; nt++) {
                int n = n0 + wn + nt * 8 + tg * 2;
                float vx = acc[mt][nt][i * 2 + 0] + bias[n];
                float vy = acc[mt][nt][i * 2 + 1] + bias[n + 1];
                float2 v;
                if (ROUND_OUT) {
                    v.x = __uint_as_float(f2tf(vx));
                    v.y = __uint_as_float(f2tf(vy));
                } else {
                    v.x = vx;
                    v.y = vy;
                }
                if (HEAD_OUT) {
                    int bI = m >> 11, s = m & (SS - 1);
                    int h = n >> 6, dh = n & 63;
                    *(float2*)&out[(((size_t)(bI * HH + h) * SS + s) << 6) + dh] = v;
                } else {
                    *(float2*)&out[(size_t)m * DD + n] = v;
                }
            }
        }
    }
}

__global__ void __launch_bounds__(128, 2) proj_kernel(
    const float* __restrict__ bq, const float* __restrict__ bk,
    const float* __restrict__ bv) {
    int z = blockIdx.z;
    const float* A = (z == 0) ? g_qr : (z == 1) ? g_kr : g_vr;
    const float* W = (z == 0) ? g_wq : (z == 1) ? g_wk : g_wv;
    const float* bias = (z == 0) ? bq : (z == 1) ? bk : bv;
    float* out = (z == 0) ? g_qh : (z == 1) ? g_kh : g_vh;
    gemm_tc<true, true>(A, W, bias, out);
}

__global__ void __launch_bounds__(128, 2) oproj_kernel(
    const float* __restrict__ bo, float* __restrict__ out) {
    gemm_tc<false, false>(g_att, g_wo, bo, out);
}

// ---------------------------------------------------------------------------
// Tensor-core flash attention, cp.async double-buffered K/V (as R4).
// Epilogue rounds outputs to tf32 values for oproj.
// ---------------------------------------------------------------------------
#define KST 68
#define VST 72
#define PST 68
#define OFF_K0 0
#define OFF_K1 (64 * KST)
#define OFF_V0 (2 * 64 * KST)
#define OFF_V1 (2 * 64 * KST + 64 * VST)
#define OFF_P (2 * 64 * KST + 2 * 64 * VST)
#define ATT_SMEM ((2 * 64 * KST + 2 * 64 * VST + 64 * PST) * 4)

__global__ void __launch_bounds__(128) attn_kernel(const int* __restrict__ mask) {
    extern __shared__ uint32_t smu[];
    const int t = threadIdx.x;
    const int lane = t & 31, w = t >> 5;
    const int g = lane >> 2, tg = lane & 3;
    const int qb = blockIdx.x;
    const int bh = blockIdx.y;
    const int b = bh >> 4, h = bh & 15;
    const size_t base = (size_t)bh * SS * DHH;
    const float* Qp = g_qh + base;
    const float* Kp = g_kh + base;
    const float* Vp = g_vh + base;

    const int lr = t >> 4, lc = (t & 15) * 4;

    auto stageKV = [&](int buf, int kb) {
        uint32_t* sK = smu + (buf ? OFF_K1 : OFF_K0);
        uint32_t* sV = smu + (buf ? OFF_V1 : OFF_V0);
#pragma unroll
        for (int i = 0; i < 8; i++) {
            int r = lr + i * 8;
            cp16(&sK[r * KST + lc], &Kp[(size_t)(kb * 64 + r) * 64 + lc]);
            cp16(&sV[r * VST + lc], &Vp[(size_t)(kb * 64 + r) * 64 + lc]);
        }
        CP_COMMIT();
    };
    stageKV(0, 0);

    uint32_t* sP = smu + OFF_P;
#pragma unroll
    for (int i = 0; i < 8; i++) {
        int r = lr + i * 8;
        *(float4*)&sP[r * PST + lc] = *(const float4*)&Qp[(size_t)(qb * 64 + r) * 64 + lc];
    }
    __syncthreads();
    uint32_t aq[8][4];
    {
        const int r0 = (w * 16 + g) * PST, r1 = (w * 16 + g + 8) * PST;
#pragma unroll
        for (int ks = 0; ks < 8; ks++) {
            aq[ks][0] = sP[r0 + ks * 8 + tg];
            aq[ks][1] = sP[r1 + ks * 8 + tg];
            aq[ks][2] = sP[r0 + ks * 8 + 4 + tg];
            aq[ks][3] = sP[r1 + ks * 8 + 4 + tg];
        }
    }
    __syncthreads();

    float m0 = -INFINITY, m1 = -INFINITY, l0 = 0.f, l1 = 0.f;
    float o[8][4];
#pragma unroll
    for (int nt = 0; nt < 8; nt++)
#pragma unroll
        for (int i = 0; i < 4; i++) o[nt][i] = 0.f;

    const float scale = 0.125f;
    const int row0g = qb * 64 + w * 16 + g;

    for (int kb = 0; kb <= qb; kb++) {
        const int buf = kb & 1;
        CP_WAIT0();
        __syncthreads();
        if (kb < qb) stageKV(buf ^ 1, kb + 1);

        const uint32_t* sK = smu + (buf ? OFF_K1 : OFF_K0);
        const uint32_t* sV = smu + (buf ? OFF_V1 : OFF_V0);

        float c_[8][4];
#pragma unroll
        for (int nt = 0; nt < 8; nt++)
#pragma unroll
            for (int i = 0; i < 4; i++) c_[nt][i] = 0.f;
#pragma unroll
        for (int ks = 0; ks < 8; ks++) {
            uint32_t bf[8][2];
#pragma unroll
            for (int nt = 0; nt < 8; nt++) {
                int cb = (nt * 8 + g) * KST;
                bf[nt][0] = sK[cb + ks * 8 + tg];
                bf[nt][1] = sK[cb + ks * 8 + 4 + tg];
            }
#pragma unroll
            for (int nt = 0; nt < 8; nt++) mma_tf32(c_[nt], aq[ks], bf[nt]);
        }

        const int colb = kb * 64 + tg * 2;
#pragma unroll
        for (int nt = 0; nt < 8; nt++) {
            int col = colb + nt * 8;
            int mk0 = __ldg(&mask[b * SS + col]);
            int mk1 = __ldg(&mask[b * SS + col + 1]);
#pragma unroll
            for (int hh = 0; hh < 2; hh++) {
                int row = row0g + hh * 8;
                float v0 = c_[nt][hh * 2] * scale;
                float v1 = c_[nt][hh * 2 + 1] * scale;
                if (mk0 == 0 || (kb == qb && col > row)) v0 = -INFINITY;
                if (mk1 == 0 || (kb == qb && col + 1 > row)) v1 = -INFINITY;
                c_[nt][hh * 2] = v0;
                c_[nt][hh * 2 + 1] = v1;
            }
        }

#pragma unroll
        for (int hh = 0; hh < 2; hh++) {
            float mprev = hh ? m1 : m0;
            float rm = -INFINITY;
#pragma unroll
            for (int nt = 0; nt < 8; nt++)
                rm = fmaxf(rm, fmaxf(c_[nt][hh * 2], c_[nt][hh * 2 + 1]));
            rm = fmaxf(rm, __shfl_xor_sync(0xffffffffu, rm, 1));
            rm = fmaxf(rm, __shfl_xor_sync(0xffffffffu, rm, 2));
            float mn = fmaxf(mprev, rm);
            float scl = __expf(mprev - mn);
            float ps = 0.f;
#pragma unroll
            for (int nt = 0; nt < 8; nt++) {
                float p0 = __expf(c_[nt][hh * 2] - mn);
                float p1 = __expf(c_[nt][hh * 2 + 1] - mn);
                c_[nt][hh * 2] = p0;
                c_[nt][hh * 2 + 1] = p1;
                ps += p0 + p1;
            }
            ps += __shfl_xor_sync(0xffffffffu, ps, 1);
            ps += __shfl_xor_sync(0xffffffffu, ps, 2);
            if (hh) {
                l1 = l1 * scl + ps;
                m1 = mn;
            } else {
                l0 = l0 * scl + ps;
                m0 = mn;
            }
#pragma unroll
            for (int nt = 0; nt < 8; nt++) {
                o[nt][hh * 2] *= scl;
                o[nt][hh * 2 + 1] *= scl;
            }
        }

        {
            const int r0 = (w * 16 + g) * PST, r1 = (w * 16 + g + 8) * PST;
#pragma unroll
            for (int nt = 0; nt < 8; nt++) {
                uint2 u0 = {f2tf(c_[nt][0]), f2tf(c_[nt][1])};
                *(uint2*)&sP[r0 + nt * 8 + tg * 2] = u0;
                uint2 u1 = {f2tf(c_[nt][2]), f2tf(c_[nt][3])};
                *(uint2*)&sP[r1 + nt * 8 + tg * 2] = u1;
            }
        }
        __syncwarp();

        {
            const int r0 = (w * 16 + g) * PST, r1 = (w * 16 + g + 8) * PST;
#pragma unroll
            for (int kk = 0; kk < 8; kk++) {
                uint32_t ap[4];
                ap[0] = sP[r0 + kk * 8 + tg];
                ap[1] = sP[r1 + kk * 8 + tg];
                ap[2] = sP[r0 + kk * 8 + 4 + tg];
                ap[3] = sP[r1 + kk * 8 + 4 + tg];
                uint32_t bv[8][2];
#pragma unroll
                for (int nt = 0; nt < 8; nt++) {
                    bv[nt][0] = sV[(kk * 8 + tg) * VST + nt * 8 + g];
                    bv[nt][1] = sV[(kk * 8 + tg + 4) * VST + nt * 8 + g];
                }
#pragma unroll
                for (int nt = 0; nt < 8; nt++) mma_tf32(o[nt], ap, bv[nt]);
            }
        }
    }

    // Epilogue: normalize + round to tf32 values for oproj
    float inv0 = 1.f / l0, inv1 = 1.f / l1;
#pragma unroll
    for (int nt = 0; nt < 8; nt++) {
        int d = h * 64 + nt * 8 + tg * 2;
        float2 v0 = {__uint_as_float(f2tf(o[nt][0] * inv0)),
                     __uint_as_float(f2tf(o[nt][1] * inv0))};
        *(float2*)&g_att[(size_t)(b * SS + row0g) * DD + d] = v0;
        float2 v1 = {__uint_as_float(f2tf(o[nt][2] * inv1)),
                     __uint_as_float(f2tf(o[nt][3] * inv1))};
        *(float2*)&g_att[(size_t)(b * SS + row0g + 8) * DD + d] = v1;
    }
}

// ---------------------------------------------------------------------------
extern "C" void kernel_launch(void* const* d_in, const int* in_sizes, int n_in,
                              void* d_out, int out_size) {
    const float* Q = (const float*)d_in[0];
    const float* K = (const float*)d_in[1];
    const float* V = (const float*)d_in[2];
    const int* mask = (const int*)d_in[3];
    const float* bq = (const float*)d_in[5];
    const float* bk = (const float*)d_in[7];
    const float* bv = (const float*)d_in[9];
    const float* Wq = (const float*)d_in[4];
    const float* Wk = (const float*)d_in[6];
    const float* Wv = (const float*)d_in[8];
    const float* Wo = (const float*)d_in[10];
    const float* bo = (const float*)d_in[11];
    float* out = (float*)d_out;

    const int gemm_smem = 2 * GSTAGE * (int)sizeof(float);  // 73728 B
    static int configured = 0;
    if (!configured) {
        cudaFuncSetAttribute(proj_kernel, cudaFuncAttributeMaxDynamicSharedMemorySize,
                             gemm_smem);
        cudaFuncSetAttribute(oproj_kernel, cudaFuncAttributeMaxDynamicSharedMemorySize,
                             gemm_smem);
        cudaFuncSetAttribute(attn_kernel, cudaFuncAttributeMaxDynamicSharedMemorySize,
                             ATT_SMEM);
        configured = 1;
    }

    // Pre-round all GEMM operands to tf32 values
    dim3 ground(512, 1, 7);
    round_kernel<<<ground, 256>>>(Q, K, V, Wq, Wk, Wv, Wo);

    dim3 gproj(DD / 128, (BB * SS) / 128, 3);
    proj_kernel<<<gproj, 128, gemm_smem>>>(bq, bk, bv);

    dim3 gattn(SS / 64, BB * HH);
    attn_kernel<<<gattn, 128, ATT_SMEM>>>(mask);

    dim3 gout(DD / 128, (BB * SS) / 128);
    oproj_kernel<<<gout, 128, gemm_smem>>>(bo, out);
}